// round 1
// baseline (speedup 1.0000x reference)
#include <cuda_runtime.h>
#include <math.h>

// Problem constants
#define BATCH 4
#define NSEQ  4096
#define DIM   512
#define KH    64
#define MTOT  (BATCH*NSEQ)      // 16384
#define NCH   32                // prefix-scan chunks per batch
#define CHLEN (NSEQ/NCH)        // 128

// ---------------- scratch (device globals; no allocation in kernel_launch) ---------
__device__ __align__(16) float g_h[MTOT*KH];          // 4 MB projected feats
__device__ float g_t1[MTOT];
__device__ float g_t2[MTOT];
__device__ float g_t2s[BATCH][NSEQ];                  // t2 sorted descending
__device__ int   g_perm[BATCH][NSEQ];
__device__ float g_e1[BATCH][NSEQ];                   // exp(t2s - m2)
__device__ float g_e2[BATCH][NSEQ];                   // exp(0.2*(t2s - m2))
__device__ __align__(16) float g_A[BATCH][NSEQ+1][KH];   // prefix of e1*h (desc order)
__device__ __align__(16) float g_B[BATCH][NSEQ+1][KH];   // prefix of e2*h
__device__ float g_Z1[BATCH][NSEQ+1];
__device__ float g_Z2[BATCH][NSEQ+1];
__device__ float g_tot1[BATCH][NCH][KH];
__device__ float g_tot2[BATCH][NCH][KH];
__device__ float g_totz1[BATCH][NCH];
__device__ float g_totz2[BATCH][NCH];
__device__ float g_off1[BATCH][NCH][KH];
__device__ float g_off2[BATCH][NCH][KH];
__device__ float g_offz1[BATCH][NCH];
__device__ float g_offz2[BATCH][NCH];

// ---------------- K1: h[m,k] = sum_d x[m,d] * Wa[k,d] --------------------------------
// Block tile 128(M) x 64(K-full), d-chunks of 16. 256 threads, 8x4 outputs/thread.
__global__ void k_gemm(const float* __restrict__ x, const float* __restrict__ Wa) {
    __shared__ __align__(16) float Xs[16*132];   // [dd][m], padded 132 (conflict-free)
    __shared__ __align__(16) float Ws[16*64];    // [dd][k]
    const int t  = threadIdx.x;          // 0..255
    const int m0 = blockIdx.x * 128;
    const int tm = t >> 4;               // 0..15 -> rows tm*8..tm*8+7
    const int tk = t & 15;               // 0..15 -> cols tk*4..tk*4+3

    float acc[8][4];
#pragma unroll
    for (int i = 0; i < 8; i++) { acc[i][0]=0.f; acc[i][1]=0.f; acc[i][2]=0.f; acc[i][3]=0.f; }

    for (int d0 = 0; d0 < DIM; d0 += 16) {
        // fill Xs: 512 float4 global loads, 2 per thread (coalesced along d)
#pragma unroll
        for (int l = 0; l < 2; l++) {
            int q  = t + l*256;
            int dg = q & 3;              // which 4-d group
            int m  = q >> 2;             // 0..127
            float4 v = *reinterpret_cast<const float4*>(x + (size_t)(m0+m)*DIM + d0 + dg*4);
            Xs[(dg*4+0)*132 + m] = v.x;
            Xs[(dg*4+1)*132 + m] = v.y;
            Xs[(dg*4+2)*132 + m] = v.z;
            Xs[(dg*4+3)*132 + m] = v.w;
        }
        // fill Ws: 64k x 16dd = 256 float4, 1 per thread
        {
            int dg = t & 3;
            int k  = t >> 2;             // 0..63
            float4 v = *reinterpret_cast<const float4*>(Wa + (size_t)k*DIM + d0 + dg*4);
            Ws[(dg*4+0)*64 + k] = v.x;
            Ws[(dg*4+1)*64 + k] = v.y;
            Ws[(dg*4+2)*64 + k] = v.z;
            Ws[(dg*4+3)*64 + k] = v.w;
        }
        __syncthreads();
#pragma unroll
        for (int dd = 0; dd < 16; dd++) {
            float4 x0 = *reinterpret_cast<const float4*>(Xs + dd*132 + tm*8);
            float4 x1 = *reinterpret_cast<const float4*>(Xs + dd*132 + tm*8 + 4);
            float4 wv = *reinterpret_cast<const float4*>(Ws + dd*64 + tk*4);
            float xv[8] = {x0.x,x0.y,x0.z,x0.w,x1.x,x1.y,x1.z,x1.w};
#pragma unroll
            for (int i = 0; i < 8; i++) {
                acc[i][0] += xv[i]*wv.x;
                acc[i][1] += xv[i]*wv.y;
                acc[i][2] += xv[i]*wv.z;
                acc[i][3] += xv[i]*wv.w;
            }
        }
        __syncthreads();
    }
#pragma unroll
    for (int i = 0; i < 8; i++) {
        int m = m0 + tm*8 + i;
        *reinterpret_cast<float4*>(g_h + (size_t)m*KH + tk*4) =
            make_float4(acc[i][0],acc[i][1],acc[i][2],acc[i][3]);
    }
}

// ---------------- K2: t1 = h.Wb + wb_bias ; t2 = h.Wc + wc_bias ----------------------
__global__ void k_t12(const float* __restrict__ Wb, const float* __restrict__ wb_bias,
                      const float* __restrict__ Wc, const float* __restrict__ wc_bias) {
    int warp = threadIdx.x >> 5, lane = threadIdx.x & 31;
    int row  = blockIdx.x * 8 + warp;
    const float* hr = g_h + (size_t)row*KH;
    float h0 = hr[lane], h1 = hr[lane+32];
    float v1 = h0*Wb[lane] + h1*Wb[lane+32];
    float v2 = h0*Wc[lane] + h1*Wc[lane+32];
#pragma unroll
    for (int s = 16; s; s >>= 1) {
        v1 += __shfl_xor_sync(0xFFFFFFFFu, v1, s);
        v2 += __shfl_xor_sync(0xFFFFFFFFu, v2, s);
    }
    if (lane == 0) { g_t1[row] = v1 + wb_bias[0]; g_t2[row] = v2 + wc_bias[0]; }
}

// ---------------- K3: per-batch bitonic sort of t2 (descending) + exp tables ---------
__global__ void k_sort() {
    __shared__ float v[NSEQ];
    __shared__ int   ix[NSEQ];
    int b = blockIdx.x, tid = threadIdx.x;   // 1024 threads
    for (int r = tid; r < NSEQ; r += 1024) { v[r] = g_t2[b*NSEQ + r]; ix[r] = r; }
    __syncthreads();
    for (int k = 2; k <= NSEQ; k <<= 1) {
        for (int s = k >> 1; s > 0; s >>= 1) {
#pragma unroll 1
            for (int t = tid; t < NSEQ/2; t += 1024) {
                int i = 2*s*(t/s) + (t % s);
                int j = i + s;
                bool desc = ((i & k) == 0);
                float vi = v[i], vj = v[j];
                bool sw = desc ? (vi < vj) : (vi > vj);
                if (sw) { v[i]=vj; v[j]=vi; int tmp=ix[i]; ix[i]=ix[j]; ix[j]=tmp; }
            }
            __syncthreads();
        }
    }
    float m2 = v[0];
    for (int r = tid; r < NSEQ; r += 1024) {
        float val = v[r];
        g_t2s[b][r]  = val;
        g_perm[b][r] = ix[r];
        g_e1[b][r]   = expf(val - m2);           // <= 1
        g_e2[b][r]   = expf(0.2f*(val - m2));    // <= 1
    }
}

// ---------------- K4a: per-chunk totals of e1*h, e2*h (and scalar z) -----------------
__global__ void k_psum_a() {
    int b = blockIdx.x >> 5;
    int c = blockIdx.x & 31;
    int k = threadIdx.x;                  // 64 threads
    int r0 = c * CHLEN;
    float s1=0.f, s2=0.f, z1=0.f, z2=0.f;
#pragma unroll 4
    for (int r = r0; r < r0 + CHLEN; r++) {
        float e1 = g_e1[b][r], e2 = g_e2[b][r];
        int   j  = g_perm[b][r];
        float hv = g_h[((size_t)b*NSEQ + j)*KH + k];
        s1 += e1*hv;  s2 += e2*hv;
        z1 += e1;     z2 += e2;
    }
    g_tot1[b][c][k] = s1;  g_tot2[b][c][k] = s2;
    if (k == 0) { g_totz1[b][c] = z1; g_totz2[b][c] = z2; }
}

// ---------------- K4b: exclusive scan of chunk totals ---------------------------------
__global__ void k_scan() {
    int tid = threadIdx.x;                // 256 threads
    int b = tid >> 6, k = tid & 63;
    float s = 0.f;
    for (int c = 0; c < NCH; c++) { g_off1[b][c][k] = s; s += g_tot1[b][c][k]; }
    s = 0.f;
    for (int c = 0; c < NCH; c++) { g_off2[b][c][k] = s; s += g_tot2[b][c][k]; }
    if (tid < BATCH) {
        int bb = tid;
        float z = 0.f; for (int c = 0; c < NCH; c++) { g_offz1[bb][c] = z; z += g_totz1[bb][c]; }
        z = 0.f;       for (int c = 0; c < NCH; c++) { g_offz2[bb][c] = z; z += g_totz2[bb][c]; }
    }
}

// ---------------- K4c: write full prefix arrays A, B, Z1, Z2 --------------------------
__global__ void k_psum_c() {
    int b = blockIdx.x >> 5;
    int c = blockIdx.x & 31;
    int k = threadIdx.x;
    int r0 = c * CHLEN;
    float s1 = g_off1[b][c][k], s2 = g_off2[b][c][k];
    float z1 = g_offz1[b][c],   z2 = g_offz2[b][c];
    if (c == 0) {
        g_A[b][0][k] = 0.f;  g_B[b][0][k] = 0.f;
        if (k == 0) { g_Z1[b][0] = 0.f; g_Z2[b][0] = 0.f; }
    }
#pragma unroll 4
    for (int r = r0; r < r0 + CHLEN; r++) {
        float e1 = g_e1[b][r], e2 = g_e2[b][r];
        int   j  = g_perm[b][r];
        float hv = g_h[((size_t)b*NSEQ + j)*KH + k];
        s1 += e1*hv;  s2 += e2*hv;
        g_A[b][r+1][k] = s1;
        g_B[b][r+1][k] = s2;
        z1 += e1;  z2 += e2;
        if (k == 0) { g_Z1[b][r+1] = z1; g_Z2[b][r+1] = z2; }
    }
}

// ---------------- K5: per-row output -------------------------------------------------
// out[b,i,k] = (c1*A[p] + c2*(Btot - B[p])) / (c1*Z1[p] + c2*(Z2tot - Z2[p])) + bias[k]
__global__ void k_out(float* __restrict__ out, const float* __restrict__ bias) {
    int t   = threadIdx.x;                // 256 = 4 rows x 64 k
    int row = blockIdx.x*4 + (t >> 6);
    int k   = t & 63;
    int b   = row >> 12;                  // row / 4096

    float t1v = g_t1[row];
    float m2  = g_t2s[b][0];
    float u   = t1v + m2;
    float M   = (u > 0.f) ? u : 0.2f*u;   // leaky_relu(u) = row max logit
    float c1  = expf(u - M);              // <= 1
    float c2  = expf(0.2f*u - M);         // <= 1
    float tau = -t1v;

    // p = #{ j : t2_j > tau } via binary search on descending t2s
    int lo = 0, hi = NSEQ;
    while (lo < hi) {
        int mid = (lo + hi) >> 1;
        if (g_t2s[b][mid] > tau) lo = mid + 1; else hi = mid;
    }
    int p = lo;

    float Btot  = g_B[b][NSEQ][k];
    float Z2tot = g_Z2[b][NSEQ];
    float num = c1*g_A[b][p][k] + c2*(Btot  - g_B[b][p][k]);
    float den = c1*g_Z1[b][p]   + c2*(Z2tot - g_Z2[b][p]);   // >= ~1 by construction
    out[(size_t)row*KH + k] = num/den + bias[k];
}

// ---------------- launch --------------------------------------------------------------
extern "C" void kernel_launch(void* const* d_in, const int* in_sizes, int n_in,
                              void* d_out, int out_size) {
    const float* x       = (const float*)d_in[0];
    const float* Wa      = (const float*)d_in[1];
    const float* Wb      = (const float*)d_in[2];
    const float* wb_bias = (const float*)d_in[3];
    const float* Wc      = (const float*)d_in[4];
    const float* wc_bias = (const float*)d_in[5];
    const float* bias    = (const float*)d_in[6];
    float* out = (float*)d_out;

    k_gemm  <<<MTOT/128, 256>>>(x, Wa);
    k_t12   <<<MTOT/8,   256>>>(Wb, wb_bias, Wc, wc_bias);
    k_sort  <<<BATCH,   1024>>>();
    k_psum_a<<<BATCH*NCH,  64>>>();
    k_scan  <<<1,        256>>>();
    k_psum_c<<<BATCH*NCH,  64>>>();
    k_out   <<<MTOT/4,   256>>>(out, bias);
}